// round 1
// baseline (speedup 1.0000x reference)
#include <cuda_runtime.h>
#include <math.h>

#define HID 768
#define NHEAD 12
#define HDIM 64
#define FF 3072
#define NLAYER 12
#define WIN 256

// ---------------- scratch (device globals; no allocation allowed) -------------
__device__ float g_x[4096 * 768];
__device__ float g_q[4096 * 768];
__device__ float g_k[4096 * 768];
__device__ float g_v[4096 * 768];
__device__ float g_a[4096 * 768];
__device__ float g_t[4096 * 768];
__device__ float g_h[4096 * 3072];
__device__ float g_emb[16 * 768];

// ---------------- SGEMM: C[M,N] = A[M,K] @ B[K,N] + bias[N] -------------------
// BM=BN=128, BK=8, 256 threads, 8x8 per thread, double buffered.
// Requires M%128==0, N%128==0, K%8==0 (true for all shapes used).
__global__ __launch_bounds__(256, 2)
void sgemm_bias(const float* __restrict__ A, const float* __restrict__ B,
                const float* __restrict__ bias, float* __restrict__ C,
                int M, int N, int K)
{
    __shared__ __align__(16) float As[2][8][128];
    __shared__ __align__(16) float Bs[2][8][128];
    const int tid  = threadIdx.x;
    const int row0 = blockIdx.y * 128;
    const int col0 = blockIdx.x * 128;
    const int tx   = tid & 15, ty = tid >> 4;

    const int a_row = tid >> 1;
    const int a_col = (tid & 1) << 2;
    const int b_row = tid >> 5;
    const int b_col = (tid & 31) << 2;

    const float* Ap = A + (size_t)(row0 + a_row) * K + a_col;
    const float* Bp = B + (size_t)b_row * N + col0 + b_col;

    float4 a4 = *(const float4*)Ap;
    float4 b4 = *(const float4*)Bp;
    As[0][a_col + 0][a_row] = a4.x;
    As[0][a_col + 1][a_row] = a4.y;
    As[0][a_col + 2][a_row] = a4.z;
    As[0][a_col + 3][a_row] = a4.w;
    *(float4*)&Bs[0][b_row][b_col] = b4;
    __syncthreads();

    float acc[8][8];
#pragma unroll
    for (int i = 0; i < 8; i++)
#pragma unroll
        for (int j = 0; j < 8; j++) acc[i][j] = 0.f;

    const int nk = K >> 3;
    for (int kt = 0; kt < nk; kt++) {
        const int cur = kt & 1;
        if (kt + 1 < nk) {
            a4 = *(const float4*)(Ap + (size_t)(kt + 1) * 8);
            b4 = *(const float4*)(Bp + (size_t)(kt + 1) * 8 * N);
        }
#pragma unroll
        for (int k = 0; k < 8; k++) {
            float ra[8], rb[8];
            *(float4*)&ra[0] = *(const float4*)&As[cur][k][ty * 8];
            *(float4*)&ra[4] = *(const float4*)&As[cur][k][ty * 8 + 4];
            *(float4*)&rb[0] = *(const float4*)&Bs[cur][k][tx * 8];
            *(float4*)&rb[4] = *(const float4*)&Bs[cur][k][tx * 8 + 4];
#pragma unroll
            for (int i = 0; i < 8; i++)
#pragma unroll
                for (int j = 0; j < 8; j++) acc[i][j] += ra[i] * rb[j];
        }
        if (kt + 1 < nk) {
            const int nxt = cur ^ 1;
            As[nxt][a_col + 0][a_row] = a4.x;
            As[nxt][a_col + 1][a_row] = a4.y;
            As[nxt][a_col + 2][a_row] = a4.z;
            As[nxt][a_col + 3][a_row] = a4.w;
            *(float4*)&Bs[nxt][b_row][b_col] = b4;
        }
        __syncthreads();
    }

#pragma unroll
    for (int i = 0; i < 8; i++) {
        const size_t r = (size_t)(row0 + ty * 8 + i);
#pragma unroll
        for (int j = 0; j < 8; j += 4) {
            const int c = col0 + tx * 8 + j;
            float4 o;
            o.x = acc[i][j + 0] + bias[c + 0];
            o.y = acc[i][j + 1] + bias[c + 1];
            o.z = acc[i][j + 2] + bias[c + 2];
            o.w = acc[i][j + 3] + bias[c + 3];
            *(float4*)&C[r * N + c] = o;
        }
    }
}

// ---------------- embedding + layernorm ---------------------------------------
__global__ __launch_bounds__(256)
void embed_ln_kernel(const int* __restrict__ ids, const float* __restrict__ we,
                     const float* __restrict__ pe, const float* __restrict__ tt,
                     const float* __restrict__ g, const float* __restrict__ bta,
                     float* __restrict__ x, int S)
{
    const int tok = blockIdx.x;
    const int s   = tok % S;
    const int tid = threadIdx.x;
    const int id  = ids[tok];
    __shared__ float red[256];
    float v[3];
    float sum = 0.f;
#pragma unroll
    for (int i = 0; i < 3; i++) {
        const int dd = tid + i * 256;
        float t = we[(size_t)id * 768 + dd] + pe[(size_t)(s + 2) * 768 + dd] + tt[dd];
        v[i] = t;
        sum += t;
    }
    red[tid] = sum;
    __syncthreads();
    for (int st = 128; st > 0; st >>= 1) { if (tid < st) red[tid] += red[tid + st]; __syncthreads(); }
    const float mu = red[0] * (1.f / 768.f);
    __syncthreads();
    float vs = 0.f;
#pragma unroll
    for (int i = 0; i < 3; i++) { float dv = v[i] - mu; vs += dv * dv; }
    red[tid] = vs;
    __syncthreads();
    for (int st = 128; st > 0; st >>= 1) { if (tid < st) red[tid] += red[tid + st]; __syncthreads(); }
    const float rstd = rsqrtf(red[0] * (1.f / 768.f) + 1e-5f);
    const size_t base = (size_t)tok * 768;
#pragma unroll
    for (int i = 0; i < 3; i++) {
        const int dd = tid + i * 256;
        x[base + dd] = (v[i] - mu) * rstd * g[dd] + bta[dd];
    }
}

// ---------------- x = LN(x + delta) -------------------------------------------
__global__ __launch_bounds__(256)
void add_ln_kernel(float* __restrict__ x, const float* __restrict__ dlt,
                   const float* __restrict__ g, const float* __restrict__ bta)
{
    const int tok = blockIdx.x;
    const int tid = threadIdx.x;
    __shared__ float red[256];
    const size_t base = (size_t)tok * 768;
    float v[3];
    float sum = 0.f;
#pragma unroll
    for (int i = 0; i < 3; i++) {
        const int dd = tid + i * 256;
        float t = x[base + dd] + dlt[base + dd];
        v[i] = t;
        sum += t;
    }
    red[tid] = sum;
    __syncthreads();
    for (int st = 128; st > 0; st >>= 1) { if (tid < st) red[tid] += red[tid + st]; __syncthreads(); }
    const float mu = red[0] * (1.f / 768.f);
    __syncthreads();
    float vs = 0.f;
#pragma unroll
    for (int i = 0; i < 3; i++) { float dv = v[i] - mu; vs += dv * dv; }
    red[tid] = vs;
    __syncthreads();
    for (int st = 128; st > 0; st >>= 1) { if (tid < st) red[tid] += red[tid + st]; __syncthreads(); }
    const float rstd = rsqrtf(red[0] * (1.f / 768.f) + 1e-5f);
#pragma unroll
    for (int i = 0; i < 3; i++) {
        const int dd = tid + i * 256;
        x[base + dd] = (v[i] - mu) * rstd * g[dd] + bta[dd];
    }
}

// ---------------- exact gelu ----------------------------------------------------
__global__ __launch_bounds__(256)
void gelu_kernel(float* __restrict__ h)
{
    const size_t i = (size_t)blockIdx.x * 256 + threadIdx.x;
    const float t = h[i];
    h[i] = 0.5f * t * (1.f + erff(t * 0.70710678118654752f));
}

// ---------------- sliding-window attention -------------------------------------
// One block (128 thr) per (b, s, h). Window = [s-256, s+256] clipped to [0,S),
// masked by amask. Q/K/V/O are in (B, S, H*D) layout (no transpose needed).
__global__ __launch_bounds__(128)
void attn_kernel(const float* __restrict__ Q, const float* __restrict__ K,
                 const float* __restrict__ V, const int* __restrict__ amask,
                 float* __restrict__ O, int S)
{
    const int s = blockIdx.x, b = blockIdx.y, h = blockIdx.z;
    const int tid = threadIdx.x;
    __shared__ float qs[64];
    __shared__ float sc[513];
    __shared__ float red[128];
    __shared__ float obuf[64];
    const size_t base = (size_t)b * S * 768 + h * 64;
    if (tid < 64) qs[tid] = Q[base + (size_t)s * 768 + tid];
    __syncthreads();
    int j0 = s - WIN; if (j0 < 0) j0 = 0;
    int j1 = s + WIN; if (j1 > S - 1) j1 = S - 1;
    const int nk = j1 - j0 + 1;

    float lmax = -1e30f;
    for (int jj = tid; jj < nk; jj += 128) {
        const int j = j0 + jj;
        const float* kp = K + base + (size_t)j * 768;
        float acc = 0.f;
#pragma unroll
        for (int d = 0; d < 64; d++) acc += qs[d] * kp[d];
        acc *= 0.125f;
        if (amask[b * S + j] == 0) acc = -1e9f;
        sc[jj] = acc;
        lmax = fmaxf(lmax, acc);
    }
    red[tid] = lmax;
    __syncthreads();
    for (int st = 64; st > 0; st >>= 1) { if (tid < st) red[tid] = fmaxf(red[tid], red[tid + st]); __syncthreads(); }
    const float m = red[0];
    __syncthreads();

    float lsum = 0.f;
    for (int jj = tid; jj < nk; jj += 128) {
        const float e = __expf(sc[jj] - m);
        sc[jj] = e;
        lsum += e;
    }
    red[tid] = lsum;
    __syncthreads();
    for (int st = 64; st > 0; st >>= 1) { if (tid < st) red[tid] += red[tid + st]; __syncthreads(); }
    const float inv = 1.f / red[0];

    const int d = tid & 63, part = tid >> 6;
    float acc = 0.f;
    for (int jj = part; jj < nk; jj += 2)
        acc += sc[jj] * V[base + (size_t)(j0 + jj) * 768 + d];
    if (part) obuf[d] = acc;
    __syncthreads();
    if (!part) O[base + (size_t)s * 768 + d] = (acc + obuf[d]) * inv;
}

// ---------------- span pooling ---------------------------------------------------
__global__ __launch_bounds__(256)
void span_pool_kernel(const float* __restrict__ seq, const float* __restrict__ masks,
                      const int* __restrict__ sidx, float* __restrict__ emb, int S)
{
    const int t = blockIdx.x;
    const int b = sidx[t];
    const int tid = threadIdx.x;
    float acc0 = 0.f, acc1 = 0.f, acc2 = 0.f, msum = 0.f;
    for (int s = 0; s < S; s++) {
        const float m = masks[(size_t)t * S + s];
        msum += m;
        const float* row = seq + (size_t)(b * S + s) * 768;
        acc0 += m * row[tid];
        acc1 += m * row[tid + 256];
        acc2 += m * row[tid + 512];
    }
    const float inv = 1.f / fmaxf(msum, 1e-9f);
    emb[(size_t)t * 768 + tid]       = acc0 * inv;
    emb[(size_t)t * 768 + tid + 256] = acc1 * inv;
    emb[(size_t)t * 768 + tid + 512] = acc2 * inv;
}

// ---------------- projection head: relu(emb@pW1+pb1)@pW2+pb2, L2-normalize ------
__global__ __launch_bounds__(256)
void proj_kernel(const float* __restrict__ emb, const float* __restrict__ pW1,
                 const float* __restrict__ pb1, const float* __restrict__ pW2,
                 const float* __restrict__ pb2, float* __restrict__ out)
{
    const int t = blockIdx.x;
    const int tid = threadIdx.x;
    __shared__ float e[768];
    __shared__ float hdn[768];
    __shared__ float o[128];
    __shared__ float red[256];
    for (int d = tid; d < 768; d += 256) e[d] = emb[(size_t)t * 768 + d];
    __syncthreads();
    for (int j = tid; j < 768; j += 256) {
        float acc = pb1[j];
        for (int d = 0; d < 768; d++) acc += e[d] * pW1[(size_t)d * 768 + j];
        hdn[j] = fmaxf(acc, 0.f);
    }
    __syncthreads();
    if (tid < 128) {
        float acc = pb2[tid];
        for (int j = 0; j < 768; j++) acc += hdn[j] * pW2[(size_t)j * 128 + tid];
        o[tid] = acc;
    }
    __syncthreads();
    red[tid] = (tid < 128) ? o[tid] * o[tid] : 0.f;
    __syncthreads();
    for (int st = 128; st > 0; st >>= 1) { if (tid < st) red[tid] += red[tid + st]; __syncthreads(); }
    const float inv = 1.f / fmaxf(sqrtf(red[0]), 1e-12f);
    if (tid < 128) out[(size_t)t * 128 + tid] = o[tid] * inv;
}

// ---------------- driver ----------------------------------------------------------
extern "C" void kernel_launch(void* const* d_in, const int* in_sizes, int n_in,
                              void* d_out, int out_size)
{
    const int*   doc_ids   = (const int*)d_in[0];
    const int*   doc_mask  = (const int*)d_in[1];
    const int*   sum_ids   = (const int*)d_in[2];
    const int*   sum_mask  = (const int*)d_in[3];
    const float* og_masks  = (const float*)d_in[4];
    const float* llm_masks = (const float*)d_in[5];
    const int*   sidx      = (const int*)d_in[6];
    const float* word_emb  = (const float*)d_in[7];
    const float* pos_emb   = (const float*)d_in[8];
    const float* tt_emb    = (const float*)d_in[9];
    const float* ln_emb_g  = (const float*)d_in[10];
    const float* ln_emb_b  = (const float*)d_in[11];
    const float* Wq = (const float*)d_in[12];
    const float* bq = (const float*)d_in[13];
    const float* Wk = (const float*)d_in[14];
    const float* bk = (const float*)d_in[15];
    const float* Wv = (const float*)d_in[16];
    const float* bv = (const float*)d_in[17];
    const float* Wo = (const float*)d_in[18];
    const float* bo = (const float*)d_in[19];
    const float* ln1_g = (const float*)d_in[20];
    const float* ln1_b = (const float*)d_in[21];
    const float* W1 = (const float*)d_in[22];
    const float* b1 = (const float*)d_in[23];
    const float* W2 = (const float*)d_in[24];
    const float* b2 = (const float*)d_in[25];
    const float* ln2_g = (const float*)d_in[26];
    const float* ln2_b = (const float*)d_in[27];
    const float* pW1 = (const float*)d_in[28];
    const float* pb1 = (const float*)d_in[29];
    const float* pW2 = (const float*)d_in[30];
    const float* pb2 = (const float*)d_in[31];
    float* out = (float*)d_out;

    float *x, *q, *k, *v, *a, *tmp, *h, *emb;
    cudaGetSymbolAddress((void**)&x, g_x);
    cudaGetSymbolAddress((void**)&q, g_q);
    cudaGetSymbolAddress((void**)&k, g_k);
    cudaGetSymbolAddress((void**)&v, g_v);
    cudaGetSymbolAddress((void**)&a, g_a);
    cudaGetSymbolAddress((void**)&tmp, g_t);
    cudaGetSymbolAddress((void**)&h, g_h);
    cudaGetSymbolAddress((void**)&emb, g_emb);

    auto encode = [&](const int* ids, const int* amask, int B, int S) {
        const int T = B * S;
        embed_ln_kernel<<<T, 256>>>(ids, word_emb, pos_emb, tt_emb, ln_emb_g, ln_emb_b, x, S);
        for (int l = 0; l < NLAYER; l++) {
            const size_t wo = (size_t)l * 768 * 768;
            const size_t w1o = (size_t)l * 768 * 3072;
            const size_t w2o = (size_t)l * 3072 * 768;
            dim3 g768(6, T / 128), g3072(24, T / 128);
            sgemm_bias<<<g768, 256>>>(x, Wq + wo, bq + l * 768, q, T, 768, 768);
            sgemm_bias<<<g768, 256>>>(x, Wk + wo, bk + l * 768, k, T, 768, 768);
            sgemm_bias<<<g768, 256>>>(x, Wv + wo, bv + l * 768, v, T, 768, 768);
            attn_kernel<<<dim3(S, B, NHEAD), 128>>>(q, k, v, amask, a, S);
            sgemm_bias<<<g768, 256>>>(a, Wo + wo, bo + l * 768, tmp, T, 768, 768);
            add_ln_kernel<<<T, 256>>>(x, tmp, ln1_g + l * 768, ln1_b + l * 768);
            sgemm_bias<<<g3072, 256>>>(x, W1 + w1o, b1 + l * 3072, h, T, 3072, 768);
            gelu_kernel<<<(T * 3072) / 256, 256>>>(h);
            sgemm_bias<<<g768, 256>>>(h, W2 + w2o, b2 + l * 768, tmp, T, 768, 3072);
            add_ln_kernel<<<T, 256>>>(x, tmp, ln2_g + l * 768, ln2_b + l * 768);
        }
    };

    // doc pass -> human embeddings
    encode(doc_ids, doc_mask, 2, 2048);
    span_pool_kernel<<<16, 256>>>(x, og_masks, sidx, emb, 2048);
    proj_kernel<<<16, 256>>>(emb, pW1, pb1, pW2, pb2, out);

    // summary pass -> llm embeddings
    encode(sum_ids, sum_mask, 2, 512);
    span_pool_kernel<<<16, 256>>>(x, llm_masks, sidx, emb, 512);
    proj_kernel<<<16, 256>>>(emb, pW1, pb1, pW2, pb2, out + 16 * 128);
}

// round 2
// speedup vs baseline: 2.6015x; 2.6015x over previous
#include <cuda_runtime.h>
#include <math.h>

#define HID 768
#define NHEAD 12
#define HDIM 64
#define FF 3072
#define NLAYER 12
#define WIN 256

// ---------------- scratch (device globals; no allocation allowed) -------------
__device__ float g_x[4096 * 768];
__device__ float g_qkv[4096 * 2304];
__device__ float g_a[4096 * 768];
__device__ float g_t[4096 * 768];
__device__ float g_h[4096 * 3072];
__device__ float g_wqkv[768 * 2304];
__device__ float g_bqkv[2304];
__device__ float g_emb[16 * 768];

// ---------------- SGEMM: C[M,N] = A[M,K] @ B[K,N] + bias[N] (+optional GELU) ---
// BM=BN=128, BK=8, 256 threads, 8x8 per thread, double buffered.
// Requires M%128==0, N%128==0, K%8==0 (true for all shapes used).
template <bool GELU>
__global__ __launch_bounds__(256, 2)
void sgemm_bias(const float* __restrict__ A, const float* __restrict__ B,
                const float* __restrict__ bias, float* __restrict__ C,
                int M, int N, int K)
{
    __shared__ __align__(16) float As[2][8][128];
    __shared__ __align__(16) float Bs[2][8][128];
    const int tid  = threadIdx.x;
    const int row0 = blockIdx.y * 128;
    const int col0 = blockIdx.x * 128;
    const int tx   = tid & 15, ty = tid >> 4;

    const int a_row = tid >> 1;
    const int a_col = (tid & 1) << 2;
    const int b_row = tid >> 5;
    const int b_col = (tid & 31) << 2;

    const float* Ap = A + (size_t)(row0 + a_row) * K + a_col;
    const float* Bp = B + (size_t)b_row * N + col0 + b_col;

    float4 a4 = *(const float4*)Ap;
    float4 b4 = *(const float4*)Bp;
    As[0][a_col + 0][a_row] = a4.x;
    As[0][a_col + 1][a_row] = a4.y;
    As[0][a_col + 2][a_row] = a4.z;
    As[0][a_col + 3][a_row] = a4.w;
    *(float4*)&Bs[0][b_row][b_col] = b4;
    __syncthreads();

    float acc[8][8];
#pragma unroll
    for (int i = 0; i < 8; i++)
#pragma unroll
        for (int j = 0; j < 8; j++) acc[i][j] = 0.f;

    const int nk = K >> 3;
    for (int kt = 0; kt < nk; kt++) {
        const int cur = kt & 1;
        if (kt + 1 < nk) {
            a4 = *(const float4*)(Ap + (size_t)(kt + 1) * 8);
            b4 = *(const float4*)(Bp + (size_t)(kt + 1) * 8 * N);
        }
#pragma unroll
        for (int k = 0; k < 8; k++) {
            float ra[8], rb[8];
            *(float4*)&ra[0] = *(const float4*)&As[cur][k][ty * 8];
            *(float4*)&ra[4] = *(const float4*)&As[cur][k][ty * 8 + 4];
            *(float4*)&rb[0] = *(const float4*)&Bs[cur][k][tx * 8];
            *(float4*)&rb[4] = *(const float4*)&Bs[cur][k][tx * 8 + 4];
#pragma unroll
            for (int i = 0; i < 8; i++)
#pragma unroll
                for (int j = 0; j < 8; j++) acc[i][j] += ra[i] * rb[j];
        }
        if (kt + 1 < nk) {
            const int nxt = cur ^ 1;
            As[nxt][a_col + 0][a_row] = a4.x;
            As[nxt][a_col + 1][a_row] = a4.y;
            As[nxt][a_col + 2][a_row] = a4.z;
            As[nxt][a_col + 3][a_row] = a4.w;
            *(float4*)&Bs[nxt][b_row][b_col] = b4;
        }
        __syncthreads();
    }

#pragma unroll
    for (int i = 0; i < 8; i++) {
        const size_t r = (size_t)(row0 + ty * 8 + i);
#pragma unroll
        for (int j = 0; j < 8; j += 4) {
            const int c = col0 + tx * 8 + j;
            float4 o;
            o.x = acc[i][j + 0] + bias[c + 0];
            o.y = acc[i][j + 1] + bias[c + 1];
            o.z = acc[i][j + 2] + bias[c + 2];
            o.w = acc[i][j + 3] + bias[c + 3];
            if (GELU) {
                o.x = 0.5f * o.x * (1.f + erff(o.x * 0.70710678118654752f));
                o.y = 0.5f * o.y * (1.f + erff(o.y * 0.70710678118654752f));
                o.z = 0.5f * o.z * (1.f + erff(o.z * 0.70710678118654752f));
                o.w = 0.5f * o.w * (1.f + erff(o.w * 0.70710678118654752f));
            }
            *(float4*)&C[r * N + c] = o;
        }
    }
}

// ---------------- pack Wq|Wk|Wv -> [768, 2304] (and biases) ---------------------
__global__ __launch_bounds__(256)
void pack_qkv_kernel(const float* __restrict__ Wq, const float* __restrict__ Wk,
                     const float* __restrict__ Wv, const float* __restrict__ bq,
                     const float* __restrict__ bk, const float* __restrict__ bv,
                     float* __restrict__ W, float* __restrict__ bias)
{
    const int i = blockIdx.x * 256 + threadIdx.x;   // 0 .. 768*768-1
    const int k = i / 768, n = i % 768;
    const size_t o = (size_t)k * 2304 + n;
    W[o]        = Wq[i];
    W[o + 768]  = Wk[i];
    W[o + 1536] = Wv[i];
    if (i < 768) { bias[i] = bq[i]; bias[768 + i] = bk[i]; bias[1536 + i] = bv[i]; }
}

// ---------------- embedding + layernorm ---------------------------------------
__global__ __launch_bounds__(256)
void embed_ln_kernel(const int* __restrict__ ids, const float* __restrict__ we,
                     const float* __restrict__ pe, const float* __restrict__ tt,
                     const float* __restrict__ g, const float* __restrict__ bta,
                     float* __restrict__ x, int S)
{
    const int tok = blockIdx.x;
    const int s   = tok % S;
    const int tid = threadIdx.x;
    const int id  = ids[tok];
    __shared__ float red[256];
    float v[3];
    float sum = 0.f;
#pragma unroll
    for (int i = 0; i < 3; i++) {
        const int dd = tid + i * 256;
        float t = we[(size_t)id * 768 + dd] + pe[(size_t)(s + 2) * 768 + dd] + tt[dd];
        v[i] = t;
        sum += t;
    }
    red[tid] = sum;
    __syncthreads();
    for (int st = 128; st > 0; st >>= 1) { if (tid < st) red[tid] += red[tid + st]; __syncthreads(); }
    const float mu = red[0] * (1.f / 768.f);
    __syncthreads();
    float vs = 0.f;
#pragma unroll
    for (int i = 0; i < 3; i++) { float dv = v[i] - mu; vs += dv * dv; }
    red[tid] = vs;
    __syncthreads();
    for (int st = 128; st > 0; st >>= 1) { if (tid < st) red[tid] += red[tid + st]; __syncthreads(); }
    const float rstd = rsqrtf(red[0] * (1.f / 768.f) + 1e-5f);
    const size_t base = (size_t)tok * 768;
#pragma unroll
    for (int i = 0; i < 3; i++) {
        const int dd = tid + i * 256;
        x[base + dd] = (v[i] - mu) * rstd * g[dd] + bta[dd];
    }
}

// ---------------- x = LN(x + delta) -------------------------------------------
__global__ __launch_bounds__(256)
void add_ln_kernel(float* __restrict__ x, const float* __restrict__ dlt,
                   const float* __restrict__ g, const float* __restrict__ bta)
{
    const int tok = blockIdx.x;
    const int tid = threadIdx.x;
    __shared__ float red[256];
    const size_t base = (size_t)tok * 768;
    float v[3];
    float sum = 0.f;
#pragma unroll
    for (int i = 0; i < 3; i++) {
        const int dd = tid + i * 256;
        float t = x[base + dd] + dlt[base + dd];
        v[i] = t;
        sum += t;
    }
    red[tid] = sum;
    __syncthreads();
    for (int st = 128; st > 0; st >>= 1) { if (tid < st) red[tid] += red[tid + st]; __syncthreads(); }
    const float mu = red[0] * (1.f / 768.f);
    __syncthreads();
    float vs = 0.f;
#pragma unroll
    for (int i = 0; i < 3; i++) { float dv = v[i] - mu; vs += dv * dv; }
    red[tid] = vs;
    __syncthreads();
    for (int st = 128; st > 0; st >>= 1) { if (tid < st) red[tid] += red[tid + st]; __syncthreads(); }
    const float rstd = rsqrtf(red[0] * (1.f / 768.f) + 1e-5f);
#pragma unroll
    for (int i = 0; i < 3; i++) {
        const int dd = tid + i * 256;
        x[base + dd] = (v[i] - mu) * rstd * g[dd] + bta[dd];
    }
}

// ---------------- sliding-window attention (coalesced, warp-per-key) -----------
// One block (128 thr = 4 warps) per (b, s, h). QKV packed rows of 2304 floats:
// q at [0,768), k at [768,1536), v at [1536,2304) within each token row.
__global__ __launch_bounds__(128)
void attn_kernel(const float* __restrict__ QKV, const int* __restrict__ amask,
                 float* __restrict__ O, int S)
{
    const int s = blockIdx.x, b = blockIdx.y, h = blockIdx.z;
    const int tid = threadIdx.x, lane = tid & 31, warp = tid >> 5;
    __shared__ float sc[513];
    __shared__ float redm[4], reds[4];
    __shared__ float obuf[3][64];

    const size_t RS = 2304;
    const size_t base = (size_t)b * S * RS + (size_t)h * 64;
    const float* Q = QKV + base;
    const float* K = QKV + base + 768;
    const float* V = QKV + base + 1536;

    int j0 = s - WIN; if (j0 < 0) j0 = 0;
    int j1 = s + WIN; if (j1 > S - 1) j1 = S - 1;
    const int nk = j1 - j0 + 1;

    const float2 q2 = *(const float2*)&Q[(size_t)s * RS + 2 * lane];

    // scores: one warp per key, coalesced 256B K-row read, shuffle reduce
    float lmax = -1e30f;
    for (int jj = warp; jj < nk; jj += 4) {
        const int j = j0 + jj;
        const float2 k2 = *(const float2*)&K[(size_t)j * RS + 2 * lane];
        float p = q2.x * k2.x + q2.y * k2.y;
#pragma unroll
        for (int off = 16; off; off >>= 1) p += __shfl_xor_sync(0xffffffffu, p, off);
        p *= 0.125f;
        if (amask[b * S + j] == 0) p = -1e9f;
        if (lane == 0) sc[jj] = p;
        lmax = fmaxf(lmax, p);
    }
    if (lane == 0) redm[warp] = lmax;
    __syncthreads();
    const float m = fmaxf(fmaxf(redm[0], redm[1]), fmaxf(redm[2], redm[3]));

    // softmax numerator + sum
    float lsum = 0.f;
    for (int jj = tid; jj < nk; jj += 128) {
        const float e = __expf(sc[jj] - m);
        sc[jj] = e;
        lsum += e;
    }
#pragma unroll
    for (int off = 16; off; off >>= 1) lsum += __shfl_xor_sync(0xffffffffu, lsum, off);
    if (lane == 0) reds[warp] = lsum;
    __syncthreads();
    const float inv = 1.f / (reds[0] + reds[1] + reds[2] + reds[3]);

    // output: 4-way key split, lanes cover 64 dims as float2 (coalesced V reads)
    float accx = 0.f, accy = 0.f;
    for (int jj = warp; jj < nk; jj += 4) {
        const float p = sc[jj];
        const float2 v2 = *(const float2*)&V[(size_t)(j0 + jj) * RS + 2 * lane];
        accx += p * v2.x;
        accy += p * v2.y;
    }
    if (warp) { obuf[warp - 1][2 * lane] = accx; obuf[warp - 1][2 * lane + 1] = accy; }
    __syncthreads();
    if (warp == 0) {
        accx += obuf[0][2 * lane] + obuf[1][2 * lane] + obuf[2][2 * lane];
        accy += obuf[0][2 * lane + 1] + obuf[1][2 * lane + 1] + obuf[2][2 * lane + 1];
        float2 o2 = make_float2(accx * inv, accy * inv);
        *(float2*)&O[((size_t)b * S + s) * 768 + h * 64 + 2 * lane] = o2;
    }
}

// ---------------- span pooling ---------------------------------------------------
__global__ __launch_bounds__(256)
void span_pool_kernel(const float* __restrict__ seq, const float* __restrict__ masks,
                      const int* __restrict__ sidx, float* __restrict__ emb, int S)
{
    const int t = blockIdx.x;
    const int b = sidx[t];
    const int tid = threadIdx.x;
    float acc0 = 0.f, acc1 = 0.f, acc2 = 0.f, msum = 0.f;
    for (int s = 0; s < S; s++) {
        const float m = masks[(size_t)t * S + s];
        msum += m;
        const float* row = seq + (size_t)(b * S + s) * 768;
        acc0 += m * row[tid];
        acc1 += m * row[tid + 256];
        acc2 += m * row[tid + 512];
    }
    const float inv = 1.f / fmaxf(msum, 1e-9f);
    emb[(size_t)t * 768 + tid]       = acc0 * inv;
    emb[(size_t)t * 768 + tid + 256] = acc1 * inv;
    emb[(size_t)t * 768 + tid + 512] = acc2 * inv;
}

// ---------------- projection head: relu(emb@pW1+pb1)@pW2+pb2, L2-normalize ------
__global__ __launch_bounds__(256)
void proj_kernel(const float* __restrict__ emb, const float* __restrict__ pW1,
                 const float* __restrict__ pb1, const float* __restrict__ pW2,
                 const float* __restrict__ pb2, float* __restrict__ out)
{
    const int t = blockIdx.x;
    const int tid = threadIdx.x;
    __shared__ float e[768];
    __shared__ float hdn[768];
    __shared__ float o[128];
    __shared__ float red[256];
    for (int d = tid; d < 768; d += 256) e[d] = emb[(size_t)t * 768 + d];
    __syncthreads();
    for (int j = tid; j < 768; j += 256) {
        float acc = pb1[j];
        for (int d = 0; d < 768; d++) acc += e[d] * pW1[(size_t)d * 768 + j];
        hdn[j] = fmaxf(acc, 0.f);
    }
    __syncthreads();
    if (tid < 128) {
        float acc = pb2[tid];
        for (int j = 0; j < 768; j++) acc += hdn[j] * pW2[(size_t)j * 128 + tid];
        o[tid] = acc;
    }
    __syncthreads();
    red[tid] = (tid < 128) ? o[tid] * o[tid] : 0.f;
    __syncthreads();
    for (int st = 128; st > 0; st >>= 1) { if (tid < st) red[tid] += red[tid + st]; __syncthreads(); }
    const float inv = 1.f / fmaxf(sqrtf(red[0]), 1e-12f);
    if (tid < 128) out[(size_t)t * 128 + tid] = o[tid] * inv;
}

// ---------------- driver ----------------------------------------------------------
extern "C" void kernel_launch(void* const* d_in, const int* in_sizes, int n_in,
                              void* d_out, int out_size)
{
    const int*   doc_ids   = (const int*)d_in[0];
    const int*   doc_mask  = (const int*)d_in[1];
    const int*   sum_ids   = (const int*)d_in[2];
    const int*   sum_mask  = (const int*)d_in[3];
    const float* og_masks  = (const float*)d_in[4];
    const float* llm_masks = (const float*)d_in[5];
    const int*   sidx      = (const int*)d_in[6];
    const float* word_emb  = (const float*)d_in[7];
    const float* pos_emb   = (const float*)d_in[8];
    const float* tt_emb    = (const float*)d_in[9];
    const float* ln_emb_g  = (const float*)d_in[10];
    const float* ln_emb_b  = (const float*)d_in[11];
    const float* Wq = (const float*)d_in[12];
    const float* bq = (const float*)d_in[13];
    const float* Wk = (const float*)d_in[14];
    const float* bk = (const float*)d_in[15];
    const float* Wv = (const float*)d_in[16];
    const float* bv = (const float*)d_in[17];
    const float* Wo = (const float*)d_in[18];
    const float* bo = (const float*)d_in[19];
    const float* ln1_g = (const float*)d_in[20];
    const float* ln1_b = (const float*)d_in[21];
    const float* W1 = (const float*)d_in[22];
    const float* b1 = (const float*)d_in[23];
    const float* W2 = (const float*)d_in[24];
    const float* b2 = (const float*)d_in[25];
    const float* ln2_g = (const float*)d_in[26];
    const float* ln2_b = (const float*)d_in[27];
    const float* pW1 = (const float*)d_in[28];
    const float* pb1 = (const float*)d_in[29];
    const float* pW2 = (const float*)d_in[30];
    const float* pb2 = (const float*)d_in[31];
    float* out = (float*)d_out;

    float *x, *qkv, *a, *tmp, *h, *wqkv, *bqkv, *emb;
    cudaGetSymbolAddress((void**)&x, g_x);
    cudaGetSymbolAddress((void**)&qkv, g_qkv);
    cudaGetSymbolAddress((void**)&a, g_a);
    cudaGetSymbolAddress((void**)&tmp, g_t);
    cudaGetSymbolAddress((void**)&h, g_h);
    cudaGetSymbolAddress((void**)&wqkv, g_wqkv);
    cudaGetSymbolAddress((void**)&bqkv, g_bqkv);
    cudaGetSymbolAddress((void**)&emb, g_emb);

    auto encode = [&](const int* ids, const int* amask, int B, int S) {
        const int T = B * S;
        embed_ln_kernel<<<T, 256>>>(ids, word_emb, pos_emb, tt_emb, ln_emb_g, ln_emb_b, x, S);
        for (int l = 0; l < NLAYER; l++) {
            const size_t wo  = (size_t)l * 768 * 768;
            const size_t w1o = (size_t)l * 768 * 3072;
            const size_t w2o = (size_t)l * 3072 * 768;
            dim3 g768(6, T / 128), g2304(18, T / 128), g3072(24, T / 128);

            pack_qkv_kernel<<<(768 * 768) / 256, 256>>>(Wq + wo, Wk + wo, Wv + wo,
                                                        bq + l * 768, bk + l * 768, bv + l * 768,
                                                        wqkv, bqkv);
            sgemm_bias<false><<<g2304, 256>>>(x, wqkv, bqkv, qkv, T, 2304, 768);
            attn_kernel<<<dim3(S, B, NHEAD), 128>>>(qkv, amask, a, S);
            sgemm_bias<false><<<g768, 256>>>(a, Wo + wo, bo + l * 768, tmp, T, 768, 768);
            add_ln_kernel<<<T, 256>>>(x, tmp, ln1_g + l * 768, ln1_b + l * 768);
            sgemm_bias<true><<<g3072, 256>>>(x, W1 + w1o, b1 + l * 3072, h, T, 3072, 768);
            sgemm_bias<false><<<g768, 256>>>(h, W2 + w2o, b2 + l * 768, tmp, T, 768, 3072);
            add_ln_kernel<<<T, 256>>>(x, tmp, ln2_g + l * 768, ln2_b + l * 768);
        }
    };

    // doc pass -> human embeddings
    encode(doc_ids, doc_mask, 2, 2048);
    span_pool_kernel<<<16, 256>>>(x, og_masks, sidx, emb, 2048);
    proj_kernel<<<16, 256>>>(emb, pW1, pb1, pW2, pb2, out);

    // summary pass -> llm embeddings
    encode(sum_ids, sum_mask, 2, 512);
    span_pool_kernel<<<16, 256>>>(x, llm_masks, sidx, emb, 512);
    proj_kernel<<<16, 256>>>(emb, pW1, pb1, pW2, pb2, out + 16 * 128);
}